// round 4
// baseline (speedup 1.0000x reference)
#include <cuda_runtime.h>
#include <cuda_bf16.h>
#include <mma.h>
#include <stdint.h>

using namespace nvcuda;

#define NB  4
#define C   256
#define CI  128
#define NHW 4096
// theta scale: sqrt(128) (reference divides by d**-0.5) * log2(e) (attn uses ex2)
#define SCALE2 16.32374202690664f   // 11.313708498984761 * 1.4426950408889634

// Scratch (allocation-free)
__device__ __nv_bfloat16 g_Xb[NB * C * NHW];   // bf16 copy of x
__device__ __nv_bfloat16 g_W[C * 384];         // fused weights, [c][o] (theta|phi|g)
__device__ float         g_bias[384];
__device__ __nv_bfloat16 g_Q[NB * NHW * CI];   // theta, pre-scaled by SCALE2
__device__ __nv_bfloat16 g_K[NB * NHW * CI];   // phi
__device__ __nv_bfloat16 g_G[NB * NHW * CI];   // g
__device__ __nv_bfloat16 g_Y[NB * NHW * CI];   // attention output

// ---------------------------------------------------------------------------
// helpers
// ---------------------------------------------------------------------------
__device__ __forceinline__ uint32_t pack2(float a, float b) {
    __nv_bfloat162 h = __floats2bfloat162_rn(a, b);
    return *reinterpret_cast<uint32_t*>(&h);
}
__device__ __forceinline__ float ex2f(float x) {
    float y;
    asm("ex2.approx.f32 %0, %1;" : "=f"(y) : "f"(x));
    return y;
}
__device__ __forceinline__ void ldsm_x4(uint32_t* f, uint32_t addr) {
    asm volatile("ldmatrix.sync.aligned.m8n8.x4.shared.b16 {%0,%1,%2,%3}, [%4];"
                 : "=r"(f[0]), "=r"(f[1]), "=r"(f[2]), "=r"(f[3]) : "r"(addr));
}
__device__ __forceinline__ void ldsm_x4_t(uint32_t* f, uint32_t addr) {
    asm volatile("ldmatrix.sync.aligned.m8n8.x4.trans.shared.b16 {%0,%1,%2,%3}, [%4];"
                 : "=r"(f[0]), "=r"(f[1]), "=r"(f[2]), "=r"(f[3]) : "r"(addr));
}
__device__ __forceinline__ void mma16816(float* c, const uint32_t* a,
                                         uint32_t b0, uint32_t b1) {
    asm volatile("mma.sync.aligned.m16n8k16.row.col.f32.bf16.bf16.f32 "
                 "{%0,%1,%2,%3}, {%4,%5,%6,%7}, {%8,%9}, {%0,%1,%2,%3};"
                 : "+f"(c[0]), "+f"(c[1]), "+f"(c[2]), "+f"(c[3])
                 : "r"(a[0]), "r"(a[1]), "r"(a[2]), "r"(a[3]), "r"(b0), "r"(b1));
}
__device__ __forceinline__ void cp_async16(uint32_t dst, const void* src) {
    asm volatile("cp.async.cg.shared.global [%0], [%1], 16;" :: "r"(dst), "l"(src));
}
__device__ __forceinline__ void cp_commit() { asm volatile("cp.async.commit_group;"); }
__device__ __forceinline__ void cp_wait1()  { asm volatile("cp.async.wait_group 1;" ::: "memory"); }
__device__ __forceinline__ void cp_wait2()  { asm volatile("cp.async.wait_group 2;" ::: "memory"); }

// ---------------------------------------------------------------------------
// Kernel 0a: x -> bf16
// ---------------------------------------------------------------------------
__global__ void __launch_bounds__(256) cvt_x_kernel(const float* __restrict__ x)
{
    const int n4 = NB * C * NHW / 4;
    for (int i = blockIdx.x * 256 + threadIdx.x; i < n4; i += gridDim.x * 256) {
        float4 v = *(const float4*)(x + (size_t)i * 4);
        uint32_t lo = pack2(v.x, v.y);
        uint32_t hi = pack2(v.z, v.w);
        uint2 w = make_uint2(lo, hi);
        *(uint2*)(g_Xb + (size_t)i * 4) = w;
    }
}

// ---------------------------------------------------------------------------
// Kernel 0b: fused weights -> bf16 [c][384] (theta*SCALE2 | phi | g) + bias
// grid(256=c), block(384=o)
// ---------------------------------------------------------------------------
__global__ void __launch_bounds__(384) cvt_w_kernel(
        const float* __restrict__ w_theta, const float* __restrict__ b_theta,
        const float* __restrict__ w_phi,   const float* __restrict__ b_phi,
        const float* __restrict__ w_g,     const float* __restrict__ b_g)
{
    int c = blockIdx.x;
    int o = threadIdx.x;
    float v, bv;
    if (o < 128)      { v = w_theta[o * C + c] * SCALE2;        bv = b_theta[o] * SCALE2; }
    else if (o < 256) { v = w_phi[(o - 128) * C + c];           bv = b_phi[o - 128]; }
    else              { v = w_g[(o - 256) * C + c];             bv = b_g[o - 256]; }
    g_W[c * 384 + o] = __float2bfloat16(v);
    if (c == 0) g_bias[o] = bv;
}

// ---------------------------------------------------------------------------
// Kernel 1: projections GEMM. T[s,o] = sum_c Xb[c,s]*W[c,o] (+bias, route).
// grid (64 stile, 2 nsplit, 4 b), 256 threads / 8 warps (4 x 2).
// dyn smem = 69632 B. Double-buffered cp.async, k-chunks of 64.
// ---------------------------------------------------------------------------
__global__ void __launch_bounds__(256) proj_kernel()
{
    extern __shared__ char sm[];
    uint32_t sb = (uint32_t)__cvta_generic_to_shared(sm);
    // X buffers: [64c][72s] bf16 (9216 B each); W buffers: [64c][200o] bf16 (25600 B each)
    const uint32_t xs0 = sb;
    const uint32_t xs1 = sb + 9216;
    const uint32_t ws0 = sb + 18432;
    const uint32_t ws1 = sb + 44032;
    float* St = (float*)sm;                         // [64][200] fp32 (reuse, 51200 B)

    const int s0 = blockIdx.x * 64;
    const int ng = blockIdx.y;
    const int b  = blockIdx.z;
    const int t  = threadIdx.x;
    const int warp = t >> 5;
    const int wm = warp >> 1;     // 0..3 : 16 s-rows
    const int wn = warp & 1;      // 0..1 : 96 o-cols

    const __nv_bfloat16* Xg = g_Xb + (size_t)b * C * NHW;

    auto prefetch = [&](int c0, uint32_t xd, uint32_t wd) {
#pragma unroll
        for (int i = 0; i < 2; i++) {           // X: 512 chunks of 16B
            int idx = t + i * 256;
            int rr = idx >> 3, c8 = (idx & 7) * 8;
            cp_async16(xd + (rr * 72 + c8) * 2, Xg + (size_t)(c0 + rr) * NHW + s0 + c8);
        }
#pragma unroll
        for (int i = 0; i < 6; i++) {           // W: 1536 chunks
            int idx = t + i * 256;
            int rr = idx / 24, o8 = (idx % 24) * 8;
            cp_async16(wd + (rr * 200 + o8) * 2, g_W + (c0 + rr) * 384 + ng * 192 + o8);
        }
    };
    prefetch(0, xs0, ws0);  cp_commit();
    prefetch(64, xs1, ws1); cp_commit();

    wmma::fragment<wmma::accumulator, 16, 16, 16, float> acc[6];
#pragma unroll
    for (int j = 0; j < 6; j++) wmma::fill_fragment(acc[j], 0.0f);

    for (int kc = 0; kc < 4; kc++) {
        cp_wait1();
        __syncthreads();
        const __nv_bfloat16* Xs = (const __nv_bfloat16*)(sm + ((kc & 1) ? 9216 : 0));
        const __nv_bfloat16* Ws = (const __nv_bfloat16*)(sm + 18432 + ((kc & 1) ? 25600 : 0));
#pragma unroll
        for (int kk = 0; kk < 4; kk++) {
            wmma::fragment<wmma::matrix_a, 16, 16, 16, __nv_bfloat16, wmma::col_major> af;
            wmma::load_matrix_sync(af, Xs + (kk * 16) * 72 + wm * 16, 72);
#pragma unroll
            for (int j = 0; j < 6; j++) {
                wmma::fragment<wmma::matrix_b, 16, 16, 16, __nv_bfloat16, wmma::row_major> bf;
                wmma::load_matrix_sync(bf, Ws + (kk * 16) * 200 + wn * 96 + j * 16, 200);
                wmma::mma_sync(acc[j], af, bf, acc[j]);
            }
        }
        __syncthreads();
        if (kc + 2 < 4)
            prefetch((kc + 2) * 64, (kc & 1) ? xs1 : xs0, (kc & 1) ? ws1 : ws0);
        cp_commit();
    }

#pragma unroll
    for (int j = 0; j < 6; j++)
        wmma::store_matrix_sync(St + (wm * 16) * 200 + wn * 96 + j * 16, acc[j], 200,
                                wmma::mem_row_major);
    __syncthreads();

    // bias + route to Q/K/G
    for (int i = 0; i < 48; i++) {
        int idx = t + i * 256;               // 12288 = 64s * 192o
        int ss = idx / 192;
        int oc = idx % 192;
        int ocg = ng * 192 + oc;
        float v = St[ss * 200 + oc] + g_bias[ocg];
        size_t base = ((size_t)b * NHW + s0 + ss) * CI;
        if (ocg < 128)       g_Q[base + ocg]         = __float2bfloat16(v);
        else if (ocg < 256)  g_K[base + (ocg - 128)] = __float2bfloat16(v);
        else                 g_G[base + (ocg - 256)] = __float2bfloat16(v);
    }
}

// ---------------------------------------------------------------------------
// Kernel 2: flash attention, BM=128 (4 warps x 32 rows, 2 m-tiles/warp), BN=32.
// 3-stage cp.async pipeline. exp2 on register accumulators (log2e folded in Q).
// grid (32, 4), 128 threads. dyn smem = 87040 B.
// ---------------------------------------------------------------------------
__global__ void __launch_bounds__(128) attn_kernel()
{
    extern __shared__ char sm[];
    const int b  = blockIdx.y;
    const int q0 = blockIdx.x * 128;
    const int t  = threadIdx.x;
    const int warp = t >> 5;
    const int lane = t & 31;
    const int mi = lane >> 3;     // 0..3 ldmatrix sub-matrix
    const int r8 = lane & 7;

    uint32_t sb = (uint32_t)__cvta_generic_to_shared(sm);
    const uint32_t qs = sb;                        // Q: 128 x 136 bf16 = 34816 B
    // stages: K[32][136] (8704 B) + G[32][136]
    auto kstage = [&](int s) { return sb + 34816u + (uint32_t)s * 17408u; };
    auto gstage = [&](int s) { return sb + 34816u + (uint32_t)s * 17408u + 8704u; };

    const __nv_bfloat16* Qg = g_Q + ((size_t)b * NHW + q0) * CI;
    const __nv_bfloat16* Kb = g_K + (size_t)b * NHW * CI;
    const __nv_bfloat16* Gb = g_G + (size_t)b * NHW * CI;

    auto prefetch = [&](int kt, int stg) {
        uint32_t kd = kstage(stg), gd = gstage(stg);
#pragma unroll
        for (int i = 0; i < 4; i++) {          // K: 512 chunks of 16B
            int idx = t + i * 128;
            int rr = idx >> 4, c8 = (idx & 15) * 8;
            cp_async16(kd + (rr * 136 + c8) * 2, Kb + (size_t)(kt * 32 + rr) * CI + c8);
        }
#pragma unroll
        for (int i = 0; i < 4; i++) {          // G
            int idx = t + i * 128;
            int rr = idx >> 4, c8 = (idx & 15) * 8;
            cp_async16(gd + (rr * 136 + c8) * 2, Gb + (size_t)(kt * 32 + rr) * CI + c8);
        }
    };

    // group 0: Q + stage 0
#pragma unroll
    for (int i = 0; i < 16; i++) {             // Q: 2048 chunks
        int idx = t + i * 128;
        int rr = idx >> 4, c8 = (idx & 15) * 8;
        cp_async16(qs + (rr * 136 + c8) * 2, Qg + (size_t)rr * CI + c8);
    }
    prefetch(0, 0); cp_commit();
    prefetch(1, 1); cp_commit();
    prefetch(2, 2); cp_commit();

    cp_wait2();           // Q + stage0 ready
    __syncthreads();

    // Q A-fragments: 2 m-tiles x 8 k-chunks
    uint32_t qa[2][8][4];
    {
        uint32_t qbase = qs + 2u * (((warp * 32) + (mi & 1) * 8 + r8) * 136 + (mi >> 1) * 8);
#pragma unroll
        for (int mt = 0; mt < 2; mt++)
#pragma unroll
            for (int kc = 0; kc < 8; kc++)
                ldsm_x4(qa[mt][kc], qbase + 2u * (mt * 16 * 136 + kc * 16));
    }

    float O[2][16][4];
#pragma unroll
    for (int mt = 0; mt < 2; mt++)
#pragma unroll
        for (int n = 0; n < 16; n++)
#pragma unroll
            for (int j = 0; j < 4; j++) O[mt][n][j] = 0.0f;
    float rs[2][2] = {{0.f, 0.f}, {0.f, 0.f}};

    const uint32_t kln = 2u * (((mi >> 1) * 8 + r8) * 136 + (mi & 1) * 8); // K non-trans
    const uint32_t gln = 2u * (((mi & 1) * 8 + r8) * 136 + (mi >> 1) * 8); // G trans

    for (int kt = 0; kt < NHW / 32; kt++) {
        cp_wait2();
        __syncthreads();
        const int stg = kt % 3;
        const uint32_t kb = kstage(stg);
        const uint32_t gb = gstage(stg);

        // S = Q @ K^T  (2 m-tiles x 32 keys)
        float S[2][4][4];
#pragma unroll
        for (int mt = 0; mt < 2; mt++)
#pragma unroll
            for (int n = 0; n < 4; n++)
#pragma unroll
                for (int j = 0; j < 4; j++) S[mt][n][j] = 0.0f;

#pragma unroll
        for (int kc = 0; kc < 8; kc++) {
            uint32_t f0[4], f1[4];
            ldsm_x4(f0, kb + kln + 2u * (kc * 16));             // keys 0-15
            ldsm_x4(f1, kb + kln + 2u * (16 * 136 + kc * 16));  // keys 16-31
#pragma unroll
            for (int mt = 0; mt < 2; mt++) {
                mma16816(S[mt][0], qa[mt][kc], f0[0], f0[1]);
                mma16816(S[mt][1], qa[mt][kc], f0[2], f0[3]);
                mma16816(S[mt][2], qa[mt][kc], f1[0], f1[1]);
                mma16816(S[mt][3], qa[mt][kc], f1[2], f1[3]);
            }
        }

        // P = exp2(S); pack A-fragments; row sums
        uint32_t pa[2][2][4];   // [m-tile][k-chunk of 16 keys][frag]
#pragma unroll
        for (int mt = 0; mt < 2; mt++) {
#pragma unroll
            for (int p = 0; p < 2; p++) {
                float e00 = ex2f(S[mt][2 * p][0]),     e01 = ex2f(S[mt][2 * p][1]);
                float e02 = ex2f(S[mt][2 * p][2]),     e03 = ex2f(S[mt][2 * p][3]);
                float e10 = ex2f(S[mt][2 * p + 1][0]), e11 = ex2f(S[mt][2 * p + 1][1]);
                float e12 = ex2f(S[mt][2 * p + 1][2]), e13 = ex2f(S[mt][2 * p + 1][3]);
                rs[mt][0] += (e00 + e01) + (e10 + e11);
                rs[mt][1] += (e02 + e03) + (e12 + e13);
                pa[mt][p][0] = pack2(e00, e01);
                pa[mt][p][1] = pack2(e02, e03);
                pa[mt][p][2] = pack2(e10, e11);
                pa[mt][p][3] = pack2(e12, e13);
            }
        }

        // O += P @ G
#pragma unroll
        for (int p = 0; p < 2; p++) {
#pragma unroll
            for (int j2 = 0; j2 < 8; j2++) {
                uint32_t f[4];
                ldsm_x4_t(f, gb + gln + 2u * (p * 16 * 136 + j2 * 16));
#pragma unroll
                for (int mt = 0; mt < 2; mt++) {
                    mma16816(O[mt][2 * j2],     pa[mt][p], f[0], f[1]);
                    mma16816(O[mt][2 * j2 + 1], pa[mt][p], f[2], f[3]);
                }
            }
        }

        __syncthreads();
        if (kt + 3 < NHW / 32) prefetch(kt + 3, stg);
        cp_commit();
    }

    // finalize
#pragma unroll
    for (int mt = 0; mt < 2; mt++) {
        rs[mt][0] += __shfl_xor_sync(0xffffffff, rs[mt][0], 1);
        rs[mt][0] += __shfl_xor_sync(0xffffffff, rs[mt][0], 2);
        rs[mt][1] += __shfl_xor_sync(0xffffffff, rs[mt][1], 1);
        rs[mt][1] += __shfl_xor_sync(0xffffffff, rs[mt][1], 2);
    }
    const int rA = lane >> 2;
    const int cA = (lane & 3) * 2;
#pragma unroll
    for (int mt = 0; mt < 2; mt++) {
        const float inv0 = 1.0f / rs[mt][0];
        const float inv1 = 1.0f / rs[mt][1];
        __nv_bfloat16* Yg = g_Y + ((size_t)b * NHW + q0 + warp * 32 + mt * 16) * CI;
#pragma unroll
        for (int n = 0; n < 16; n++) {
            *(uint32_t*)(Yg + (size_t)rA * CI + n * 8 + cA) =
                pack2(O[mt][n][0] * inv0, O[mt][n][1] * inv0);
            *(uint32_t*)(Yg + (size_t)(rA + 8) * CI + n * 8 + cA) =
                pack2(O[mt][n][2] * inv1, O[mt][n][3] * inv1);
        }
    }
}

// ---------------------------------------------------------------------------
// Kernel 3: out[b,o,s] = x[b,o,s] + b_out[o] + sum_c Y[b,s,c] * w_out[o,c]
// 512 threads / 16 warps. grid (64, 4). dyn smem = 84992 B.
// ---------------------------------------------------------------------------
__global__ void __launch_bounds__(512) out_kernel(
        const float* __restrict__ x, const float* __restrict__ w_out,
        const float* __restrict__ b_out, float* __restrict__ out)
{
    extern __shared__ char sm[];
    __nv_bfloat16* Ys = (__nv_bfloat16*)sm;            // [64][136]
    __nv_bfloat16* Wo = (__nv_bfloat16*)(sm + 17408);  // [128][264]
    float*         Ost = (float*)(sm + 17408);         // [64][264] (reuse)

    const int b  = blockIdx.y;
    const int s0 = blockIdx.x * 64;
    const int t  = threadIdx.x;
    const int warp = t >> 5;
    const int wm = warp >> 2;   // 0..3 : 16 s-rows
    const int wn = warp & 3;    // 0..3 : 64 o-cols

    const __nv_bfloat16* Yg = g_Y + ((size_t)b * NHW + s0) * CI;
#pragma unroll
    for (int i = 0; i < 2; i++) {
        int idx = t + i * 512;
        int r = idx >> 4, cc = (idx & 15) * 8;
        *(uint4*)&Ys[r * 136 + cc] = *(const uint4*)&Yg[(size_t)r * CI + cc];
    }
    for (int i = 0; i < 64; i++) {
        int idx = t + i * 512;               // 32768 = 128c * 256o
        int cc = idx & 127, o = idx >> 7;
        Wo[cc * 264 + o] = __float2bfloat16(w_out[o * CI + cc]);
    }
    __syncthreads();

    wmma::fragment<wmma::accumulator, 16, 16, 16, float> acc[4];
#pragma unroll
    for (int j = 0; j < 4; j++) wmma::fill_fragment(acc[j], 0.0f);
#pragma unroll
    for (int k = 0; k < 8; k++) {
        wmma::fragment<wmma::matrix_a, 16, 16, 16, __nv_bfloat16, wmma::row_major> af;
        wmma::load_matrix_sync(af, Ys + (wm * 16) * 136 + k * 16, 136);
#pragma unroll
        for (int j = 0; j < 4; j++) {
            wmma::fragment<wmma::matrix_b, 16, 16, 16, __nv_bfloat16, wmma::row_major> bf;
            wmma::load_matrix_sync(bf, Wo + (k * 16) * 264 + wn * 64 + j * 16, 264);
            wmma::mma_sync(acc[j], af, bf, acc[j]);
        }
    }
    __syncthreads();
#pragma unroll
    for (int j = 0; j < 4; j++)
        wmma::store_matrix_sync(Ost + (wm * 16) * 264 + wn * 64 + j * 16, acc[j], 264,
                                wmma::mem_row_major);
    __syncthreads();

    const float* xb = x + (size_t)b * C * NHW;
    float*       ob = out + (size_t)b * C * NHW;
    for (int i = 0; i < 32; i++) {
        int idx = t + i * 512;               // 16384 = 64s * 256o
        int ss = idx & 63, o = idx >> 6;
        ob[(size_t)o * NHW + s0 + ss] =
            Ost[ss * 264 + o] + b_out[o] + xb[(size_t)o * NHW + s0 + ss];
    }
}

// ---------------------------------------------------------------------------
extern "C" void kernel_launch(void* const* d_in, const int* in_sizes, int n_in,
                              void* d_out, int out_size)
{
    const float* x       = (const float*)d_in[0];
    const float* w_g     = (const float*)d_in[1];
    const float* b_g     = (const float*)d_in[2];
    const float* w_theta = (const float*)d_in[3];
    const float* b_theta = (const float*)d_in[4];
    const float* w_phi   = (const float*)d_in[5];
    const float* b_phi   = (const float*)d_in[6];
    const float* w_out   = (const float*)d_in[7];
    const float* b_out   = (const float*)d_in[8];
    float* out = (float*)d_out;

    cudaFuncSetAttribute(proj_kernel, cudaFuncAttributeMaxDynamicSharedMemorySize, 69632);
    cudaFuncSetAttribute(attn_kernel, cudaFuncAttributeMaxDynamicSharedMemorySize, 87040);
    cudaFuncSetAttribute(out_kernel,  cudaFuncAttributeMaxDynamicSharedMemorySize, 84992);

    cvt_x_kernel<<<1024, 256>>>(x);
    cvt_w_kernel<<<256, 384>>>(w_theta, b_theta, w_phi, b_phi, w_g, b_g);

    dim3 pgrid(64, 2, NB);
    proj_kernel<<<pgrid, 256, 69632>>>();

    dim3 agrid(32, NB);
    attn_kernel<<<agrid, 128, 87040>>>();

    dim3 ogrid(64, NB);
    out_kernel<<<ogrid, 512, 84992>>>(x, w_out, b_out, out);
}

// round 6
// speedup vs baseline: 1.6700x; 1.6700x over previous
#include <cuda_runtime.h>
#include <cuda_bf16.h>
#include <mma.h>
#include <stdint.h>

using namespace nvcuda;

#define NB  4
#define C   256
#define CI  128
#define NHW 4096
// theta scale: sqrt(128) (reference divides by d**-0.5) * log2(e) (attn uses ex2)
#define SCALE2 16.32374202690664f   // 11.313708498984761 * 1.4426950408889634

// Scratch (allocation-free)
__device__ __nv_bfloat16 g_Xb[NB * C * NHW];   // bf16 copy of x
__device__ __nv_bfloat16 g_W[C * 384];         // fused weights, [c][o] (theta|phi|g)
__device__ float         g_bias[384];
__device__ __nv_bfloat16 g_Q[NB * NHW * CI];   // theta, pre-scaled by SCALE2
__device__ __nv_bfloat16 g_K[NB * NHW * CI];   // phi
__device__ __nv_bfloat16 g_G[NB * NHW * CI];   // g
__device__ __nv_bfloat16 g_Y[NB * NHW * CI];   // attention output

// ---------------------------------------------------------------------------
// helpers
// ---------------------------------------------------------------------------
__device__ __forceinline__ uint32_t pack2(float a, float b) {
    __nv_bfloat162 h = __floats2bfloat162_rn(a, b);
    return *reinterpret_cast<uint32_t*>(&h);
}
__device__ __forceinline__ float ex2f(float x) {
    float y;
    asm("ex2.approx.f32 %0, %1;" : "=f"(y) : "f"(x));
    return y;
}
__device__ __forceinline__ void ldsm_x4(uint32_t* f, uint32_t addr) {
    asm volatile("ldmatrix.sync.aligned.m8n8.x4.shared.b16 {%0,%1,%2,%3}, [%4];"
                 : "=r"(f[0]), "=r"(f[1]), "=r"(f[2]), "=r"(f[3]) : "r"(addr));
}
__device__ __forceinline__ void ldsm_x4_t(uint32_t* f, uint32_t addr) {
    asm volatile("ldmatrix.sync.aligned.m8n8.x4.trans.shared.b16 {%0,%1,%2,%3}, [%4];"
                 : "=r"(f[0]), "=r"(f[1]), "=r"(f[2]), "=r"(f[3]) : "r"(addr));
}
__device__ __forceinline__ void mma16816(float* c, const uint32_t* a,
                                         uint32_t b0, uint32_t b1) {
    asm volatile("mma.sync.aligned.m16n8k16.row.col.f32.bf16.bf16.f32 "
                 "{%0,%1,%2,%3}, {%4,%5,%6,%7}, {%8,%9}, {%0,%1,%2,%3};"
                 : "+f"(c[0]), "+f"(c[1]), "+f"(c[2]), "+f"(c[3])
                 : "r"(a[0]), "r"(a[1]), "r"(a[2]), "r"(a[3]), "r"(b0), "r"(b1));
}
__device__ __forceinline__ void cp_async16(uint32_t dst, const void* src) {
    asm volatile("cp.async.cg.shared.global [%0], [%1], 16;" :: "r"(dst), "l"(src));
}
__device__ __forceinline__ void cp_commit() { asm volatile("cp.async.commit_group;"); }
template <int N>
__device__ __forceinline__ void cp_wait() {
    asm volatile("cp.async.wait_group %0;" :: "n"(N) : "memory");
}

// ---------------------------------------------------------------------------
// Kernel 0a: x -> bf16
// ---------------------------------------------------------------------------
__global__ void __launch_bounds__(256) cvt_x_kernel(const float* __restrict__ x)
{
    const int n4 = NB * C * NHW / 4;
    for (int i = blockIdx.x * 256 + threadIdx.x; i < n4; i += gridDim.x * 256) {
        float4 v = *(const float4*)(x + (size_t)i * 4);
        uint2 w = make_uint2(pack2(v.x, v.y), pack2(v.z, v.w));
        *(uint2*)(g_Xb + (size_t)i * 4) = w;
    }
}

// ---------------------------------------------------------------------------
// Kernel 0b: fused weights -> bf16 [c][384] (theta*SCALE2 | phi | g) + bias
// ---------------------------------------------------------------------------
__global__ void __launch_bounds__(384) cvt_w_kernel(
        const float* __restrict__ w_theta, const float* __restrict__ b_theta,
        const float* __restrict__ w_phi,   const float* __restrict__ b_phi,
        const float* __restrict__ w_g,     const float* __restrict__ b_g)
{
    int c = blockIdx.x;
    int o = threadIdx.x;
    float v, bv;
    if (o < 128)      { v = w_theta[o * C + c] * SCALE2;  bv = b_theta[o] * SCALE2; }
    else if (o < 256) { v = w_phi[(o - 128) * C + c];     bv = b_phi[o - 128]; }
    else              { v = w_g[(o - 256) * C + c];       bv = b_g[o - 256]; }
    g_W[c * 384 + o] = __float2bfloat16(v);
    if (c == 0) g_bias[o] = bv;
}

// ---------------------------------------------------------------------------
// Kernel 1: projections GEMM. T[s,o] = sum_c Xb[c,s]*W[c,o] (+bias, route).
// grid (64 stile, 2 nsplit, 4 b), 256 threads / 8 warps (4 x 2).
// dyn smem = 69632 B. Double-buffered cp.async, k-chunks of 64.
// ---------------------------------------------------------------------------
__global__ void __launch_bounds__(256) proj_kernel()
{
    extern __shared__ char sm[];
    uint32_t sb = (uint32_t)__cvta_generic_to_shared(sm);
    const uint32_t xs0 = sb;
    const uint32_t xs1 = sb + 9216;
    const uint32_t ws0 = sb + 18432;
    const uint32_t ws1 = sb + 44032;
    float* St = (float*)sm;                         // [64][200] fp32 (reuse)

    const int s0 = blockIdx.x * 64;
    const int ng = blockIdx.y;
    const int b  = blockIdx.z;
    const int t  = threadIdx.x;
    const int warp = t >> 5;
    const int wm = warp >> 1;     // 0..3 : 16 s-rows
    const int wn = warp & 1;      // 0..1 : 96 o-cols

    const __nv_bfloat16* Xg = g_Xb + (size_t)b * C * NHW;

    auto prefetch = [&](int c0, uint32_t xd, uint32_t wd) {
#pragma unroll
        for (int i = 0; i < 2; i++) {           // X: 512 chunks of 16B
            int idx = t + i * 256;
            int rr = idx >> 3, c8 = (idx & 7) * 8;
            cp_async16(xd + (rr * 72 + c8) * 2, Xg + (size_t)(c0 + rr) * NHW + s0 + c8);
        }
#pragma unroll
        for (int i = 0; i < 6; i++) {           // W: 1536 chunks
            int idx = t + i * 256;
            int rr = idx / 24, o8 = (idx % 24) * 8;
            cp_async16(wd + (rr * 200 + o8) * 2, g_W + (c0 + rr) * 384 + ng * 192 + o8);
        }
    };
    prefetch(0, xs0, ws0);  cp_commit();
    prefetch(64, xs1, ws1); cp_commit();

    wmma::fragment<wmma::accumulator, 16, 16, 16, float> acc[6];
#pragma unroll
    for (int j = 0; j < 6; j++) wmma::fill_fragment(acc[j], 0.0f);

    for (int kc = 0; kc < 4; kc++) {
        cp_wait<1>();
        __syncthreads();
        const __nv_bfloat16* Xs = (const __nv_bfloat16*)(sm + ((kc & 1) ? 9216 : 0));
        const __nv_bfloat16* Ws = (const __nv_bfloat16*)(sm + 18432 + ((kc & 1) ? 25600 : 0));
#pragma unroll
        for (int kk = 0; kk < 4; kk++) {
            wmma::fragment<wmma::matrix_a, 16, 16, 16, __nv_bfloat16, wmma::col_major> af;
            wmma::load_matrix_sync(af, Xs + (kk * 16) * 72 + wm * 16, 72);
#pragma unroll
            for (int j = 0; j < 6; j++) {
                wmma::fragment<wmma::matrix_b, 16, 16, 16, __nv_bfloat16, wmma::row_major> bf;
                wmma::load_matrix_sync(bf, Ws + (kk * 16) * 200 + wn * 96 + j * 16, 200);
                wmma::mma_sync(acc[j], af, bf, acc[j]);
            }
        }
        __syncthreads();
        if (kc + 2 < 4)
            prefetch((kc + 2) * 64, (kc & 1) ? xs1 : xs0, (kc & 1) ? ws1 : ws0);
        cp_commit();
    }

#pragma unroll
    for (int j = 0; j < 6; j++)
        wmma::store_matrix_sync(St + (wm * 16) * 200 + wn * 96 + j * 16, acc[j], 200,
                                wmma::mem_row_major);
    __syncthreads();

    // bias + route to Q/K/G
    for (int i = 0; i < 48; i++) {
        int idx = t + i * 256;               // 12288 = 64s * 192o
        int ss = idx / 192;
        int oc = idx % 192;
        int ocg = ng * 192 + oc;
        float v = St[ss * 200 + oc] + g_bias[ocg];
        size_t base = ((size_t)b * NHW + s0 + ss) * CI;
        if (ocg < 128)       g_Q[base + ocg]         = __float2bfloat16(v);
        else if (ocg < 256)  g_K[base + (ocg - 128)] = __float2bfloat16(v);
        else                 g_G[base + (ocg - 256)] = __float2bfloat16(v);
    }
}

// ---------------------------------------------------------------------------
// Kernel 2: flash attention (mma.sync), BM=128 via 8 warps x 16 rows, BN=64.
// One m-tile per warp keeps regs ~175 -> 2 warps/SMSP (vs 255 regs / 1 warp
// in the 2-m-tile variant). 3-stage cp.async pipeline. exp2 on accumulators.
// grid (32, 4), 256 threads. dyn smem = 139264 B.
// ---------------------------------------------------------------------------
__global__ void __launch_bounds__(256) attn_kernel()
{
    extern __shared__ char sm[];
    const int b  = blockIdx.y;
    const int q0 = blockIdx.x * 128;
    const int t  = threadIdx.x;
    const int warp = t >> 5;
    const int lane = t & 31;
    const int mi = lane >> 3;     // 0..3 ldmatrix sub-matrix
    const int r8 = lane & 7;

    uint32_t sb = (uint32_t)__cvta_generic_to_shared(sm);
    const uint32_t qs = sb;                        // Q: 128 x 136 bf16 = 34816 B
    // stages: K[64][136] (17408 B) + G[64][136] (17408 B) = 34816 B each
    auto kstage = [&](int s) { return sb + 34816u + (uint32_t)s * 34816u; };
    auto gstage = [&](int s) { return sb + 34816u + (uint32_t)s * 34816u + 17408u; };

    const __nv_bfloat16* Qg = g_Q + ((size_t)b * NHW + q0) * CI;
    const __nv_bfloat16* Kb = g_K + (size_t)b * NHW * CI;
    const __nv_bfloat16* Gb = g_G + (size_t)b * NHW * CI;

    auto loadKG = [&](int kt) {
        const int stg = kt % 3;
        uint32_t kd = kstage(stg), gd = gstage(stg);
#pragma unroll
        for (int i = 0; i < 4; i++) {          // K: 1024 chunks of 16B
            int idx = t + i * 256;
            int rr = idx >> 4, c8 = (idx & 15) * 8;
            cp_async16(kd + (rr * 136 + c8) * 2, Kb + (size_t)(kt * 64 + rr) * CI + c8);
        }
#pragma unroll
        for (int i = 0; i < 4; i++) {          // G
            int idx = t + i * 256;
            int rr = idx >> 4, c8 = (idx & 15) * 8;
            cp_async16(gd + (rr * 136 + c8) * 2, Gb + (size_t)(kt * 64 + rr) * CI + c8);
        }
    };

    // prologue: group0 = Q + stage0, group1 = stage1, group2 = stage2
#pragma unroll
    for (int i = 0; i < 8; i++) {              // Q: 2048 chunks
        int idx = t + i * 256;
        int rr = idx >> 4, c8 = (idx & 15) * 8;
        cp_async16(qs + (rr * 136 + c8) * 2, Qg + (size_t)rr * CI + c8);
    }
    loadKG(0); cp_commit();
    loadKG(1); cp_commit();
    loadKG(2); cp_commit();

    cp_wait<2>();           // Q + stage0 ready
    __syncthreads();

    // Q A-fragments: warp rows [warp*16, warp*16+16), 8 k-chunks of 16
    uint32_t qa[8][4];
    {
        uint32_t qbase = qs + 2u * (((warp * 16) + (mi & 1) * 8 + r8) * 136 + (mi >> 1) * 8);
#pragma unroll
        for (int kc = 0; kc < 8; kc++)
            ldsm_x4(qa[kc], qbase + 2u * (kc * 16));
    }

    float O[16][4];
#pragma unroll
    for (int n = 0; n < 16; n++)
#pragma unroll
        for (int j = 0; j < 4; j++) O[n][j] = 0.0f;
    float rs0 = 0.0f, rs1 = 0.0f;

    const uint32_t kln = 2u * (((mi >> 1) * 8 + r8) * 136 + (mi & 1) * 8); // K non-trans
    const uint32_t gln = 2u * (((mi & 1) * 8 + r8) * 136 + (mi >> 1) * 8); // G trans

    for (int kt = 0; kt < NHW / 64; kt++) {
        const int stg = kt % 3;
        const uint32_t kb = kstage(stg);
        const uint32_t gb = gstage(stg);

        // S = Q @ K^T  (16 x 64 per warp, in registers)
        float S[8][4];
#pragma unroll
        for (int n = 0; n < 8; n++)
#pragma unroll
            for (int j = 0; j < 4; j++) S[n][j] = 0.0f;

#pragma unroll
        for (int p = 0; p < 4; p++) {        // key groups of 16
#pragma unroll
            for (int kc = 0; kc < 8; kc++) {
                uint32_t f[4];
                ldsm_x4(f, kb + kln + 2u * (p * 16 * 136 + kc * 16));
                mma16816(S[2 * p],     qa[kc], f[0], f[1]);
                mma16816(S[2 * p + 1], qa[kc], f[2], f[3]);
            }
        }

        // P = exp2(S); pack to bf16x2 A-fragments; accumulate row sums
        uint32_t pa[4][4];
#pragma unroll
        for (int p = 0; p < 4; p++) {
            float e00 = ex2f(S[2 * p][0]),     e01 = ex2f(S[2 * p][1]);
            float e02 = ex2f(S[2 * p][2]),     e03 = ex2f(S[2 * p][3]);
            float e10 = ex2f(S[2 * p + 1][0]), e11 = ex2f(S[2 * p + 1][1]);
            float e12 = ex2f(S[2 * p + 1][2]), e13 = ex2f(S[2 * p + 1][3]);
            rs0 += (e00 + e01) + (e10 + e11);
            rs1 += (e02 + e03) + (e12 + e13);
            pa[p][0] = pack2(e00, e01);
            pa[p][1] = pack2(e02, e03);
            pa[p][2] = pack2(e10, e11);
            pa[p][3] = pack2(e12, e13);
        }

        // O += P @ G  (16 x 128 per warp)
#pragma unroll
        for (int p = 0; p < 4; p++) {        // key chunks of 16
#pragma unroll
            for (int j2 = 0; j2 < 8; j2++) { // ci tile pairs of 16
                uint32_t f[4];
                ldsm_x4_t(f, gb + gln + 2u * (p * 16 * 136 + j2 * 16));
                mma16816(O[2 * j2],     pa[p], f[0], f[1]);
                mma16816(O[2 * j2 + 1], pa[p], f[2], f[3]);
            }
        }

        __syncthreads();                       // all warps done with slot kt%3
        if (kt + 3 < NHW / 64) loadKG(kt + 3);
        cp_commit();
        if (kt + 1 < NHW / 64) {
            cp_wait<2>();                      // stage kt+1 ready
            __syncthreads();
        }
    }

    // finalize: row sums across quad lanes, divide, store
    rs0 += __shfl_xor_sync(0xffffffff, rs0, 1);
    rs0 += __shfl_xor_sync(0xffffffff, rs0, 2);
    rs1 += __shfl_xor_sync(0xffffffff, rs1, 1);
    rs1 += __shfl_xor_sync(0xffffffff, rs1, 2);
    const float inv0 = 1.0f / rs0;
    const float inv1 = 1.0f / rs1;

    __nv_bfloat16* Yg = g_Y + ((size_t)b * NHW + q0 + warp * 16) * CI;
    const int rA = lane >> 2;
    const int cA = (lane & 3) * 2;
#pragma unroll
    for (int n = 0; n < 16; n++) {
        *(uint32_t*)(Yg + (size_t)rA * CI + n * 8 + cA) =
            pack2(O[n][0] * inv0, O[n][1] * inv0);
        *(uint32_t*)(Yg + (size_t)(rA + 8) * CI + n * 8 + cA) =
            pack2(O[n][2] * inv1, O[n][3] * inv1);
    }
}

// ---------------------------------------------------------------------------
// Kernel 3: out[b,o,s] = x[b,o,s] + b_out[o] + sum_c Y[b,s,c] * w_out[o,c]
// 512 threads / 16 warps. grid (64, 4). dyn smem = 84992 B.
// ---------------------------------------------------------------------------
__global__ void __launch_bounds__(512) out_kernel(
        const float* __restrict__ x, const float* __restrict__ w_out,
        const float* __restrict__ b_out, float* __restrict__ out)
{
    extern __shared__ char sm[];
    __nv_bfloat16* Ys = (__nv_bfloat16*)sm;            // [64][136]
    __nv_bfloat16* Wo = (__nv_bfloat16*)(sm + 17408);  // [128][264]
    float*         Ost = (float*)(sm + 17408);         // [64][264] (reuse)

    const int b  = blockIdx.y;
    const int s0 = blockIdx.x * 64;
    const int t  = threadIdx.x;
    const int warp = t >> 5;
    const int wm = warp >> 2;   // 0..3 : 16 s-rows
    const int wn = warp & 3;    // 0..3 : 64 o-cols

    const __nv_bfloat16* Yg = g_Y + ((size_t)b * NHW + s0) * CI;
#pragma unroll
    for (int i = 0; i < 2; i++) {
        int idx = t + i * 512;
        int r = idx >> 4, cc = (idx & 15) * 8;
        *(uint4*)&Ys[r * 136 + cc] = *(const uint4*)&Yg[(size_t)r * CI + cc];
    }
    for (int i = 0; i < 64; i++) {
        int idx = t + i * 512;               // 32768 = 128c * 256o
        int cc = idx & 127, o = idx >> 7;
        Wo[cc * 264 + o] = __float2bfloat16(w_out[o * CI + cc]);
    }
    __syncthreads();

    wmma::fragment<wmma::accumulator, 16, 16, 16, float> acc[4];
#pragma unroll
    for (int j = 0; j < 4; j++) wmma::fill_fragment(acc[j], 0.0f);
#pragma unroll
    for (int k = 0; k < 8; k++) {
        wmma::fragment<wmma::matrix_a, 16, 16, 16, __nv_bfloat16, wmma::row_major> af;
        wmma::load_matrix_sync(af, Ys + (wm * 16) * 136 + k * 16, 136);
#pragma unroll
        for (int j = 0; j < 4; j++) {
            wmma::fragment<wmma::matrix_b, 16, 16, 16, __nv_bfloat16, wmma::row_major> bf;
            wmma::load_matrix_sync(bf, Wo + (k * 16) * 264 + wn * 64 + j * 16, 264);
            wmma::mma_sync(acc[j], af, bf, acc[j]);
        }
    }
    __syncthreads();
#pragma unroll
    for (int j = 0; j < 4; j++)
        wmma::store_matrix_sync(Ost + (wm * 16) * 264 + wn * 64 + j * 16, acc[j], 264,
                                wmma::mem_row_major);
    __syncthreads();

    const float* xb = x + (size_t)b * C * NHW;
    float*       ob = out + (size_t)b * C * NHW;
    for (int i = 0; i < 32; i++) {
        int idx = t + i * 512;               // 16384 = 64s * 256o
        int ss = idx & 63, o = idx >> 6;
        ob[(size_t)o * NHW + s0 + ss] =
            Ost[ss * 264 + o] + b_out[o] + xb[(size_t)o * NHW + s0 + ss];
    }
}

// ---------------------------------------------------------------------------
extern "C" void kernel_launch(void* const* d_in, const int* in_sizes, int n_in,
                              void* d_out, int out_size)
{
    const float* x       = (const float*)d_in[0];
    const float* w_g     = (const float*)d_in[1];
    const float* b_g     = (const float*)d_in[2];
    const float* w_theta = (const float*)d_in[3];
    const float* b_theta = (const float*)d_in[4];
    const float* w_phi   = (const float*)d_in[5];
    const float* b_phi   = (const float*)d_in[6];
    const float* w_out   = (const float*)d_in[7];
    const float* b_out   = (const float*)d_in[8];
    float* out = (float*)d_out;

    cudaFuncSetAttribute(proj_kernel, cudaFuncAttributeMaxDynamicSharedMemorySize, 69632);
    cudaFuncSetAttribute(attn_kernel, cudaFuncAttributeMaxDynamicSharedMemorySize, 139264);
    cudaFuncSetAttribute(out_kernel,  cudaFuncAttributeMaxDynamicSharedMemorySize, 84992);

    cvt_x_kernel<<<1024, 256>>>(x);
    cvt_w_kernel<<<256, 384>>>(w_theta, b_theta, w_phi, b_phi, w_g, b_g);

    dim3 pgrid(64, 2, NB);
    proj_kernel<<<pgrid, 256, 69632>>>();

    dim3 agrid(32, NB);
    attn_kernel<<<agrid, 256, 139264>>>();

    dim3 ogrid(64, NB);
    out_kernel<<<ogrid, 512, 84992>>>(x, w_out, b_out, out);
}